// round 14
// baseline (speedup 1.0000x reference)
#include <cuda_runtime.h>
#include <cuda_fp16.h>
#include <cstdint>
#include <cstddef>

// Problem constants
#define Bg    16
#define Ntok  512
#define Eg    131072
#define MROWS (Bg * Ntok)          // 8192
#define SCALE 0.17677669529663687f // 1/sqrt(32)

// Scratch (device globals; no allocation allowed)
__device__ __align__(16) __half g_h16[MROWS * 256];
__device__ float    g_q[MROWS * 256];
__device__ __align__(16) __half g_k16[MROWS * 256];
__device__ __align__(16) __half g_v16[MROWS * 256];
__device__ __align__(16) __half g_att16[MROWS * 256];
__device__ unsigned g_mask[Bg * Ntok * 16];  // 131072 words
// Transposed fp16 weights: [4 weights][N=256 rows][K=256 cols] K-major
__device__ __align__(16) __half g_wt[4 * 256 * 256];

// ---------------------------------------------------------------------------
// Warp-MMA helpers (portable sm_80+ path; harness PTX target is compute_100
// without 'a' suffix -> tcgen05 unavailable)
// ---------------------------------------------------------------------------
__device__ __forceinline__ void ldsm_x4(uint32_t addr, uint32_t* r) {
    asm volatile("ldmatrix.sync.aligned.m8n8.x4.shared.b16 {%0,%1,%2,%3}, [%4];"
                 : "=r"(r[0]), "=r"(r[1]), "=r"(r[2]), "=r"(r[3]) : "r"(addr));
}
__device__ __forceinline__ void ldsm_x2(uint32_t addr, uint32_t* r) {
    asm volatile("ldmatrix.sync.aligned.m8n8.x2.shared.b16 {%0,%1}, [%2];"
                 : "=r"(r[0]), "=r"(r[1]) : "r"(addr));
}
__device__ __forceinline__ void mma_f16(float* c, const uint32_t* a, const uint32_t* b) {
    asm volatile(
        "mma.sync.aligned.m16n8k16.row.col.f32.f16.f16.f32 "
        "{%0,%1,%2,%3}, {%4,%5,%6,%7}, {%8,%9}, {%0,%1,%2,%3};"
        : "+f"(c[0]), "+f"(c[1]), "+f"(c[2]), "+f"(c[3])
        : "r"(a[0]), "r"(a[1]), "r"(a[2]), "r"(a[3]), "r"(b[0]), "r"(b[1]));
}
__device__ __forceinline__ uint32_t pack_h2(__half a, __half b) {
    __half2 t(a, b);
    return *reinterpret_cast<uint32_t*>(&t);
}

// ---------------------------------------------------------------------------
// h fp32 -> fp16 (one float4 per thread; same rounding the GEMM used to do)
// ---------------------------------------------------------------------------
__global__ void hconv_kernel(const float* __restrict__ h,
                             __half* __restrict__ h16) {
    int i = blockIdx.x * 256 + threadIdx.x;       // < 524288 float4s
    float4 v = reinterpret_cast<const float4*>(h)[i];
    uint2 u;
    u.x = pack_h2(__float2half_rn(v.x), __float2half_rn(v.y));
    u.y = pack_h2(__float2half_rn(v.z), __float2half_rn(v.w));
    reinterpret_cast<uint2*>(h16)[i] = u;
}

// ---------------------------------------------------------------------------
// Weight prep: W[K=256][N=256] fp32 -> Wt[N][K] fp16 (transpose + convert)
// ---------------------------------------------------------------------------
__global__ void wconv_kernel(const float* __restrict__ Wq, const float* __restrict__ Wk,
                             const float* __restrict__ Wv, const float* __restrict__ Wo,
                             __half* __restrict__ wt) {
    const float* W = (blockIdx.z == 0) ? Wq : (blockIdx.z == 1) ? Wk
                   : (blockIdx.z == 2) ? Wv : Wo;
    __shared__ float tile[32][33];
    int tx = threadIdx.x, ty = threadIdx.y;
    int n0 = blockIdx.x * 32, k0 = blockIdx.y * 32;
#pragma unroll
    for (int j = 0; j < 4; j++)
        tile[ty + 8 * j][tx] = W[(k0 + ty + 8 * j) * 256 + n0 + tx];
    __syncthreads();
    size_t wbase = (size_t)blockIdx.z * 65536;
#pragma unroll
    for (int j = 0; j < 4; j++) {
        int n = n0 + ty + 8 * j;
        int k = k0 + tx;
        wt[wbase + (size_t)n * 256 + k] = __float2half_rn(tile[tx][ty + 8 * j]);
    }
}

// ---------------------------------------------------------------------------
// Mask build: diag (self loops) + edge scatter
// ---------------------------------------------------------------------------
__global__ void mask_init_kernel(unsigned* __restrict__ mask) {
    int idx = blockIdx.x * 256 + threadIdx.x;
    int w = idx & 15;
    int r = (idx >> 4) & 511;
    mask[idx] = ((r >> 5) == w) ? (1u << (r & 31)) : 0u;
}

__global__ void mask_edges_kernel(const int* __restrict__ src,
                                  const int* __restrict__ dst,
                                  unsigned* __restrict__ mask) {
    int i = blockIdx.x * 256 + threadIdx.x;
    int s = src[i];
    int d = dst[i];
    int b = s >> 9;
    int r = s & 511;
    int c = d & 511;
    atomicOr(&mask[((b << 9) + r) * 16 + (c >> 5)], 1u << (c & 31));
}

// ---------------------------------------------------------------------------
// fp16 GEMM (A pre-converted fp16): C[128,64] per CTA = A[128,256]@Wt^T+bias.
// 256 threads = 8 warps (4m x 2n), warp tile 32x32, m16n8k16 mma.sync.
// Double-buffered smem, one __syncthreads per K-chunk, 2 CTAs/SM.
// pf load/store are pure uint4 copies (no conversion in the hot loop).
// ---------------------------------------------------------------------------
#define KCH   32
#define NCHNK 8
#define ASTR  40                 // smem row stride in halfs (80 B)

struct Pf {
    uint4 a[2];
    uint4 b;
};

__device__ __forceinline__ void pf_load(Pf& p, const __half* __restrict__ A,
                                        const __half* __restrict__ wt,
                                        int row0, int col0, int ch, int tid) {
#pragma unroll
    for (int i = 0; i < 2; i++) {
        int idx = tid + i * 256;              // 0..511 uint4s (A: 128 rows x 4)
        int r = idx >> 2, c4 = idx & 3;
        p.a[i] = *reinterpret_cast<const uint4*>(
            A + (size_t)(row0 + r) * 256 + ch * KCH + c4 * 8);
    }
    int r = tid >> 2, q4 = tid & 3;           // B: 64 rows x 4 uint4/row
    p.b = *reinterpret_cast<const uint4*>(wt + (size_t)(col0 + r) * 256 + ch * KCH + q4 * 8);
}

__device__ __forceinline__ void pf_store(const Pf& p,
                                         __half* Ash, __half* Bsh, int tid) {
#pragma unroll
    for (int i = 0; i < 2; i++) {
        int idx = tid + i * 256;
        int r = idx >> 2, c4 = idx & 3;
        *reinterpret_cast<uint4*>(&Ash[r * ASTR + c4 * 8]) = p.a[i];
    }
    int r = tid >> 2, q4 = tid & 3;
    *reinterpret_cast<uint4*>(&Bsh[r * ASTR + q4 * 8]) = p.b;
}

__device__ __forceinline__ void mma_gemm_body(
    const __half* __restrict__ A,
    const __half* __restrict__ wt,
    const float* __restrict__ bias,
    float* __restrict__ C32, __half* __restrict__ C16,
    int row0, int col0) {
    __shared__ __align__(16) __half Ash[2][128 * ASTR];
    __shared__ __align__(16) __half Bsh[2][64 * ASTR];

    int tid  = threadIdx.x;           // 0..255
    int wid  = tid >> 5;              // 0..7
    int lane = tid & 31;
    int wrow = (wid >> 1) * 32;       // 0,32,64,96
    int wn   = (wid & 1) * 32;        // 0,32

    int arow = wrow + (lane & 15);
    int ac8  = ((lane >> 4) & 1) * 8;
    int brow = wn + (lane & 7);
    int bc8  = ((lane >> 3) & 1) * 8;

    float acc[2][4][4];
#pragma unroll
    for (int mt = 0; mt < 2; mt++)
#pragma unroll
        for (int nt = 0; nt < 4; nt++)
#pragma unroll
            for (int i = 0; i < 4; i++) acc[mt][nt][i] = 0.f;

    Pf pf;
    pf_load(pf, A, wt, row0, col0, 0, tid);
    pf_store(pf, Ash[0], Bsh[0], tid);
    __syncthreads();

#pragma unroll 1
    for (int ch = 0; ch < NCHNK; ch++) {
        if (ch + 1 < NCHNK)
            pf_load(pf, A, wt, row0, col0, ch + 1, tid);

        uint32_t a_b = (uint32_t)__cvta_generic_to_shared(Ash[ch & 1]);
        uint32_t b_b = (uint32_t)__cvta_generic_to_shared(Bsh[ch & 1]);
#pragma unroll
        for (int ks = 0; ks < 2; ks++) {
            uint32_t ah[2][4], bh[4][2];
#pragma unroll
            for (int mt = 0; mt < 2; mt++) {
                uint32_t off = (uint32_t)(((arow + mt * 16) * ASTR + ks * 16 + ac8) * 2);
                ldsm_x4(a_b + off, ah[mt]);
            }
#pragma unroll
            for (int nt = 0; nt < 4; nt++) {
                uint32_t off = (uint32_t)(((brow + nt * 8) * ASTR + ks * 16 + bc8) * 2);
                ldsm_x2(b_b + off, bh[nt]);
            }
#pragma unroll
            for (int mt = 0; mt < 2; mt++)
#pragma unroll
                for (int nt = 0; nt < 4; nt++)
                    mma_f16(acc[mt][nt], ah[mt], bh[nt]);
        }
        if (ch + 1 < NCHNK) {
            pf_store(pf, Ash[(ch + 1) & 1], Bsh[(ch + 1) & 1], tid);
            __syncthreads();
        }
    }

    // Epilogue
#pragma unroll
    for (int mt = 0; mt < 2; mt++) {
#pragma unroll
        for (int nt = 0; nt < 4; nt++) {
            int r = row0 + wrow + mt * 16 + (lane >> 2);
            int c = col0 + wn + nt * 8 + (lane & 3) * 2;
            float b0 = bias[c], b1 = bias[c + 1];
            float v00 = acc[mt][nt][0] + b0, v01 = acc[mt][nt][1] + b1;
            float v10 = acc[mt][nt][2] + b0, v11 = acc[mt][nt][3] + b1;
            if (C16) {
                *reinterpret_cast<uint32_t*>(C16 + (size_t)r * 256 + c) =
                    pack_h2(__float2half_rn(v00), __float2half_rn(v01));
                *reinterpret_cast<uint32_t*>(C16 + (size_t)(r + 8) * 256 + c) =
                    pack_h2(__float2half_rn(v10), __float2half_rn(v11));
            } else {
                *reinterpret_cast<float2*>(C32 + (size_t)r * 256 + c) =
                    make_float2(v00, v01);
                *reinterpret_cast<float2*>(C32 + (size_t)(r + 8) * 256 + c) =
                    make_float2(v10, v11);
            }
        }
    }
}

__global__ __launch_bounds__(256, 2) void mma_qkv_kernel(
    const __half* __restrict__ A, const __half* __restrict__ wt,
    const float* bq, const float* bk, const float* bv,
    float* q, __half* k16, __half* v16) {
    int wsel = blockIdx.z;
    const float* bias = (wsel == 0) ? bq : (wsel == 1) ? bk : bv;
    float* C32 = (wsel == 0) ? q : nullptr;
    __half* C16 = (wsel == 1) ? k16 : (wsel == 2) ? v16 : nullptr;
    mma_gemm_body(A, wt + (size_t)wsel * 65536, bias, C32, C16,
                  blockIdx.x * 128, blockIdx.y * 64);
}

__global__ __launch_bounds__(256, 2) void mma_o_kernel(
    const __half* __restrict__ A, const __half* __restrict__ wt,
    const float* __restrict__ bias, float* __restrict__ C) {
    mma_gemm_body(A, wt + (size_t)3 * 65536, bias, C, nullptr,
                  blockIdx.x * 128, blockIdx.y * 64);
}

// ---------------------------------------------------------------------------
// Sparse masked attention (k/v fp16 in; output fp16 -- same rounding the
// O-GEMM applied anyway, so error-neutral, but halves STG + O-GEMM LDG).
// Warp per (b,q), all 8 heads; lane owns 8 dims.
// ---------------------------------------------------------------------------
__global__ __launch_bounds__(256) void attn_kernel(
    const float* __restrict__ q, const __half* __restrict__ k,
    const __half* __restrict__ v, const unsigned* __restrict__ mask,
    __half* __restrict__ att16) {
    int gw   = blockIdx.x * 8 + (threadIdx.x >> 5);
    int lane = threadIdx.x & 31;
    int qi = gw & 511;
    int b  = gw >> 9;

    int off = lane * 8;
    size_t qrow = (size_t)gw * 256;
    float4 qa = *reinterpret_cast<const float4*>(q + qrow + off);
    float4 qb = *reinterpret_cast<const float4*>(q + qrow + off + 4);

    float m = -1e30f, l = 0.f;
    float acc[8];
#pragma unroll
    for (int d = 0; d < 8; d++) acc[d] = 0.f;

    const unsigned* mrow = mask + ((b << 9) + qi) * 16;
    size_t bbase = (size_t)(b << 9) * 256;

#pragma unroll 1
    for (int w = 0; w < 16; w++) {
        unsigned bits = mrow[w];
        while (bits) {
            int bit = __ffs(bits) - 1;
            bits &= bits - 1;
            int j = (w << 5) + bit;
            size_t rbase = bbase + (size_t)j * 256 + off;
            uint4 ku = *reinterpret_cast<const uint4*>(k + rbase);
            uint4 vu = *reinterpret_cast<const uint4*>(v + rbase);
            const __half2* kh = reinterpret_cast<const __half2*>(&ku);
            const __half2* vh = reinterpret_cast<const __half2*>(&vu);
            float2 k0 = __half22float2(kh[0]);
            float2 k1 = __half22float2(kh[1]);
            float2 k2 = __half22float2(kh[2]);
            float2 k3 = __half22float2(kh[3]);

            float s = qa.x * k0.x + qa.y * k0.y + qa.z * k1.x + qa.w * k1.y
                    + qb.x * k2.x + qb.y * k2.y + qb.z * k3.x + qb.w * k3.y;
            s += __shfl_xor_sync(0xffffffffu, s, 1);
            s += __shfl_xor_sync(0xffffffffu, s, 2);
            s *= SCALE;

            float mn   = fmaxf(m, s);
            float corr = __expf(m - mn);
            float p    = __expf(s - mn);
            l = l * corr + p;
            m = mn;
            float2 v0 = __half22float2(vh[0]);
            float2 v1 = __half22float2(vh[1]);
            float2 v2 = __half22float2(vh[2]);
            float2 v3 = __half22float2(vh[3]);
            acc[0] = acc[0] * corr + p * v0.x;
            acc[1] = acc[1] * corr + p * v0.y;
            acc[2] = acc[2] * corr + p * v1.x;
            acc[3] = acc[3] * corr + p * v1.y;
            acc[4] = acc[4] * corr + p * v2.x;
            acc[5] = acc[5] * corr + p * v2.y;
            acc[6] = acc[6] * corr + p * v3.x;
            acc[7] = acc[7] * corr + p * v3.y;
        }
    }

    float inv = 1.f / l;
    uint4 u;
    u.x = pack_h2(__float2half_rn(acc[0] * inv), __float2half_rn(acc[1] * inv));
    u.y = pack_h2(__float2half_rn(acc[2] * inv), __float2half_rn(acc[3] * inv));
    u.z = pack_h2(__float2half_rn(acc[4] * inv), __float2half_rn(acc[5] * inv));
    u.w = pack_h2(__float2half_rn(acc[6] * inv), __float2half_rn(acc[7] * inv));
    *reinterpret_cast<uint4*>(att16 + qrow + off) = u;
}

// ---------------------------------------------------------------------------
// Launch
// ---------------------------------------------------------------------------
extern "C" void kernel_launch(void* const* d_in, const int* in_sizes, int n_in,
                              void* d_out, int out_size) {
    const float* h   = (const float*)d_in[0];
    const int*   src = (const int*)d_in[1];
    const int*   dst = (const int*)d_in[2];
    const float* Wq  = (const float*)d_in[3];
    const float* bq  = (const float*)d_in[4];
    const float* Wk  = (const float*)d_in[5];
    const float* bk  = (const float*)d_in[6];
    const float* Wv  = (const float*)d_in[7];
    const float* bv  = (const float*)d_in[8];
    const float* Wo  = (const float*)d_in[9];
    const float* bo  = (const float*)d_in[10];
    float* out = (float*)d_out;

    float *pq;
    __half *ph16, *pk16, *pv16, *patt16, *pwt;
    unsigned* pmask;
    cudaGetSymbolAddress((void**)&ph16,   g_h16);
    cudaGetSymbolAddress((void**)&pq,     g_q);
    cudaGetSymbolAddress((void**)&pk16,   g_k16);
    cudaGetSymbolAddress((void**)&pv16,   g_v16);
    cudaGetSymbolAddress((void**)&patt16, g_att16);
    cudaGetSymbolAddress((void**)&pmask,  g_mask);
    cudaGetSymbolAddress((void**)&pwt,    g_wt);

    // Prep: h fp16, weight transpose + fp16, mask build (all independent)
    hconv_kernel<<<MROWS * 256 / 4 / 256, 256>>>(h, ph16);
    wconv_kernel<<<dim3(8, 8, 4), dim3(32, 8)>>>(Wq, Wk, Wv, Wo, pwt);
    mask_init_kernel<<<Bg * Ntok * 16 / 256, 256>>>(pmask);
    mask_edges_kernel<<<Eg / 256, 256>>>(src, dst, pmask);

    // Q/K/V projections (A fp16; q fp32, k/v fp16)
    mma_qkv_kernel<<<dim3(MROWS / 128, 4, 3), 256>>>(
        ph16, pwt, bq, bk, bv, pq, pk16, pv16);

    // Sparse masked attention -> fp16 output
    attn_kernel<<<MROWS / 8, 256>>>(pq, pk16, pv16, pmask, patt16);

    // Output projection straight into d_out
    mma_o_kernel<<<dim3(MROWS / 128, 4), 256>>>(patt16, pwt, bo, out);
}

// round 15
// speedup vs baseline: 1.0645x; 1.0645x over previous
#include <cuda_runtime.h>
#include <cuda_fp16.h>
#include <cstdint>
#include <cstddef>

// Problem constants
#define Bg    16
#define Ntok  512
#define Eg    131072
#define MROWS (Bg * Ntok)          // 8192
#define SCALE 0.17677669529663687f // 1/sqrt(32)

// Scratch (device globals; no allocation allowed)
// g_mask is zero-initialized at module load; attn re-zeros the words it reads
// after use, so every graph replay sees an all-zero mask before the atomics.
__device__ __align__(16) __half g_h16[MROWS * 256];
__device__ float    g_q[MROWS * 256];
__device__ __align__(16) __half g_k16[MROWS * 256];
__device__ __align__(16) __half g_v16[MROWS * 256];
__device__ __align__(16) __half g_att16[MROWS * 256];
__device__ unsigned g_mask[Bg * Ntok * 16];  // 131072 words
// Transposed fp16 weights: [4 weights][N=256 rows][K=256 cols] K-major
__device__ __align__(16) __half g_wt[4 * 256 * 256];

// ---------------------------------------------------------------------------
// Warp-MMA helpers (portable sm_80+ path; harness PTX target is compute_100
// without 'a' suffix -> tcgen05 unavailable; mma.sync HMMA is the ceiling)
// ---------------------------------------------------------------------------
__device__ __forceinline__ void ldsm_x4(uint32_t addr, uint32_t* r) {
    asm volatile("ldmatrix.sync.aligned.m8n8.x4.shared.b16 {%0,%1,%2,%3}, [%4];"
                 : "=r"(r[0]), "=r"(r[1]), "=r"(r[2]), "=r"(r[3]) : "r"(addr));
}
__device__ __forceinline__ void ldsm_x2(uint32_t addr, uint32_t* r) {
    asm volatile("ldmatrix.sync.aligned.m8n8.x2.shared.b16 {%0,%1}, [%2];"
                 : "=r"(r[0]), "=r"(r[1]) : "r"(addr));
}
__device__ __forceinline__ void mma_f16(float* c, const uint32_t* a, const uint32_t* b) {
    asm volatile(
        "mma.sync.aligned.m16n8k16.row.col.f32.f16.f16.f32 "
        "{%0,%1,%2,%3}, {%4,%5,%6,%7}, {%8,%9}, {%0,%1,%2,%3};"
        : "+f"(c[0]), "+f"(c[1]), "+f"(c[2]), "+f"(c[3])
        : "r"(a[0]), "r"(a[1]), "r"(a[2]), "r"(a[3]), "r"(b[0]), "r"(b[1]));
}
__device__ __forceinline__ uint32_t pack_h2(__half a, __half b) {
    __half2 t(a, b);
    return *reinterpret_cast<uint32_t*>(&t);
}

// ---------------------------------------------------------------------------
// Fused prep: h fp32->fp16 (blocks 0..2047) + weight transpose/convert
// (blocks 2048..2303). Independent work, one launch.
// ---------------------------------------------------------------------------
__global__ void prep_kernel(const float* __restrict__ h,
                            const float* __restrict__ Wq, const float* __restrict__ Wk,
                            const float* __restrict__ Wv, const float* __restrict__ Wo,
                            __half* __restrict__ h16, __half* __restrict__ wt) {
    __shared__ float tile[32][33];
    int bx = blockIdx.x;
    int tid = threadIdx.x;
    if (bx < 2048) {
        int i = bx * 256 + tid;                   // < 524288 float4s
        float4 v = reinterpret_cast<const float4*>(h)[i];
        uint2 u;
        u.x = pack_h2(__float2half_rn(v.x), __float2half_rn(v.y));
        u.y = pack_h2(__float2half_rn(v.z), __float2half_rn(v.w));
        reinterpret_cast<uint2*>(h16)[i] = u;
        return;
    }
    int wb   = bx - 2048;                         // 0..255
    int wsel = wb >> 6;
    int blk  = wb & 63;
    const float* W = (wsel == 0) ? Wq : (wsel == 1) ? Wk
                   : (wsel == 2) ? Wv : Wo;
    int tx = tid & 31, ty = tid >> 5;
    int n0 = (blk & 7) * 32, k0 = (blk >> 3) * 32;
#pragma unroll
    for (int j = 0; j < 4; j++)
        tile[ty + 8 * j][tx] = W[(k0 + ty + 8 * j) * 256 + n0 + tx];
    __syncthreads();
    size_t wbase = (size_t)wsel * 65536;
#pragma unroll
    for (int j = 0; j < 4; j++) {
        int n = n0 + ty + 8 * j;
        int k = k0 + tx;
        wt[wbase + (size_t)n * 256 + k] = __float2half_rn(tile[tx][ty + 8 * j]);
    }
}

// ---------------------------------------------------------------------------
// fp16 GEMM (A pre-converted fp16): C[128,64] per CTA = A[128,256]@Wt^T+bias.
// 256 threads = 8 warps (4m x 2n), warp tile 32x32, m16n8k16 mma.sync.
// Double-buffered smem, one __syncthreads per K-chunk, 2 CTAs/SM.
// ---------------------------------------------------------------------------
#define KCH   32
#define NCHNK 8
#define ASTR  40                 // smem row stride in halfs (80 B)

struct Pf {
    uint4 a[2];
    uint4 b;
};

__device__ __forceinline__ void pf_load(Pf& p, const __half* __restrict__ A,
                                        const __half* __restrict__ wt,
                                        int row0, int col0, int ch, int tid) {
#pragma unroll
    for (int i = 0; i < 2; i++) {
        int idx = tid + i * 256;              // 0..511 uint4s (A: 128 rows x 4)
        int r = idx >> 2, c4 = idx & 3;
        p.a[i] = *reinterpret_cast<const uint4*>(
            A + (size_t)(row0 + r) * 256 + ch * KCH + c4 * 8);
    }
    int r = tid >> 2, q4 = tid & 3;           // B: 64 rows x 4 uint4/row
    p.b = *reinterpret_cast<const uint4*>(wt + (size_t)(col0 + r) * 256 + ch * KCH + q4 * 8);
}

__device__ __forceinline__ void pf_store(const Pf& p,
                                         __half* Ash, __half* Bsh, int tid) {
#pragma unroll
    for (int i = 0; i < 2; i++) {
        int idx = tid + i * 256;
        int r = idx >> 2, c4 = idx & 3;
        *reinterpret_cast<uint4*>(&Ash[r * ASTR + c4 * 8]) = p.a[i];
    }
    int r = tid >> 2, q4 = tid & 3;
    *reinterpret_cast<uint4*>(&Bsh[r * ASTR + q4 * 8]) = p.b;
}

__device__ __forceinline__ void mma_gemm_body(
    const __half* __restrict__ A,
    const __half* __restrict__ wt,
    const float* __restrict__ bias,
    float* __restrict__ C32, __half* __restrict__ C16,
    int row0, int col0) {
    __shared__ __align__(16) __half Ash[2][128 * ASTR];
    __shared__ __align__(16) __half Bsh[2][64 * ASTR];

    int tid  = threadIdx.x;           // 0..255
    int wid  = tid >> 5;              // 0..7
    int lane = tid & 31;
    int wrow = (wid >> 1) * 32;       // 0,32,64,96
    int wn   = (wid & 1) * 32;        // 0,32

    int arow = wrow + (lane & 15);
    int ac8  = ((lane >> 4) & 1) * 8;
    int brow = wn + (lane & 7);
    int bc8  = ((lane >> 3) & 1) * 8;

    float acc[2][4][4];
#pragma unroll
    for (int mt = 0; mt < 2; mt++)
#pragma unroll
        for (int nt = 0; nt < 4; nt++)
#pragma unroll
            for (int i = 0; i < 4; i++) acc[mt][nt][i] = 0.f;

    Pf pf;
    pf_load(pf, A, wt, row0, col0, 0, tid);
    pf_store(pf, Ash[0], Bsh[0], tid);
    __syncthreads();

#pragma unroll 1
    for (int ch = 0; ch < NCHNK; ch++) {
        if (ch + 1 < NCHNK)
            pf_load(pf, A, wt, row0, col0, ch + 1, tid);

        uint32_t a_b = (uint32_t)__cvta_generic_to_shared(Ash[ch & 1]);
        uint32_t b_b = (uint32_t)__cvta_generic_to_shared(Bsh[ch & 1]);
#pragma unroll
        for (int ks = 0; ks < 2; ks++) {
            uint32_t ah[2][4], bh[4][2];
#pragma unroll
            for (int mt = 0; mt < 2; mt++) {
                uint32_t off = (uint32_t)(((arow + mt * 16) * ASTR + ks * 16 + ac8) * 2);
                ldsm_x4(a_b + off, ah[mt]);
            }
#pragma unroll
            for (int nt = 0; nt < 4; nt++) {
                uint32_t off = (uint32_t)(((brow + nt * 8) * ASTR + ks * 16 + bc8) * 2);
                ldsm_x2(b_b + off, bh[nt]);
            }
#pragma unroll
            for (int mt = 0; mt < 2; mt++)
#pragma unroll
                for (int nt = 0; nt < 4; nt++)
                    mma_f16(acc[mt][nt], ah[mt], bh[nt]);
        }
        if (ch + 1 < NCHNK) {
            pf_store(pf, Ash[(ch + 1) & 1], Bsh[(ch + 1) & 1], tid);
            __syncthreads();
        }
    }

    // Epilogue
#pragma unroll
    for (int mt = 0; mt < 2; mt++) {
#pragma unroll
        for (int nt = 0; nt < 4; nt++) {
            int r = row0 + wrow + mt * 16 + (lane >> 2);
            int c = col0 + wn + nt * 8 + (lane & 3) * 2;
            float b0 = bias[c], b1 = bias[c + 1];
            float v00 = acc[mt][nt][0] + b0, v01 = acc[mt][nt][1] + b1;
            float v10 = acc[mt][nt][2] + b0, v11 = acc[mt][nt][3] + b1;
            if (C16) {
                *reinterpret_cast<uint32_t*>(C16 + (size_t)r * 256 + c) =
                    pack_h2(__float2half_rn(v00), __float2half_rn(v01));
                *reinterpret_cast<uint32_t*>(C16 + (size_t)(r + 8) * 256 + c) =
                    pack_h2(__float2half_rn(v10), __float2half_rn(v11));
            } else {
                *reinterpret_cast<float2*>(C32 + (size_t)r * 256 + c) =
                    make_float2(v00, v01);
                *reinterpret_cast<float2*>(C32 + (size_t)(r + 8) * 256 + c) =
                    make_float2(v10, v11);
            }
        }
    }
}

// QKV GEMM with the mask build fused in: 768 CTAs x 256 threads cover the
// 131072 edge atomics + 8192 self-loop atomics. Issued before the GEMM body,
// their latency hides in the GEMM's idle issue slots (qkv issue ~20%).
// g_mask is all-zero on entry (module init / attn restore), so atomicOr-only
// construction needs no separate init pass.
__global__ __launch_bounds__(256, 2) void mma_qkv_kernel(
    const __half* __restrict__ A, const __half* __restrict__ wt,
    const float* bq, const float* bk, const float* bv,
    float* q, __half* k16, __half* v16,
    const int* __restrict__ src, const int* __restrict__ dst,
    unsigned* __restrict__ mask) {
    // --- fused mask build ---
    int gid = ((blockIdx.z * gridDim.y + blockIdx.y) * gridDim.x + blockIdx.x) * 256
              + threadIdx.x;                       // 0..196607
    if (gid < Eg) {
        int s = src[gid];
        int d = dst[gid];
        int b = s >> 9;
        int r = s & 511;
        int c = d & 511;
        atomicOr(&mask[((b << 9) + r) * 16 + (c >> 5)], 1u << (c & 31));
    } else if (gid < Eg + MROWS) {
        int row = gid - Eg;                        // global (b*512+qi)
        int qi = row & 511;
        atomicOr(&mask[row * 16 + (qi >> 5)], 1u << (qi & 31));
    }

    // --- GEMM ---
    int wsel = blockIdx.z;
    const float* bias = (wsel == 0) ? bq : (wsel == 1) ? bk : bv;
    float* C32 = (wsel == 0) ? q : nullptr;
    __half* C16 = (wsel == 1) ? k16 : (wsel == 2) ? v16 : nullptr;
    mma_gemm_body(A, wt + (size_t)wsel * 65536, bias, C32, C16,
                  blockIdx.x * 128, blockIdx.y * 64);
}

__global__ __launch_bounds__(256, 2) void mma_o_kernel(
    const __half* __restrict__ A, const __half* __restrict__ wt,
    const float* __restrict__ bias, float* __restrict__ C) {
    mma_gemm_body(A, wt + (size_t)3 * 65536, bias, C, nullptr,
                  blockIdx.x * 128, blockIdx.y * 64);
}

// ---------------------------------------------------------------------------
// Sparse masked attention (k/v fp16, fp16 output). Warp per (b,q), 8 heads.
// After use, each warp ZEROES its own 16 mask words, restoring the all-zero
// invariant for the next graph replay (race-free: one warp per row).
// ---------------------------------------------------------------------------
__global__ __launch_bounds__(256) void attn_kernel(
    const float* __restrict__ q, const __half* __restrict__ k,
    const __half* __restrict__ v, unsigned* __restrict__ mask,
    __half* __restrict__ att16) {
    int gw   = blockIdx.x * 8 + (threadIdx.x >> 5);
    int lane = threadIdx.x & 31;
    int qi = gw & 511;
    int b  = gw >> 9;

    int off = lane * 8;
    size_t qrow = (size_t)gw * 256;
    float4 qa = *reinterpret_cast<const float4*>(q + qrow + off);
    float4 qb = *reinterpret_cast<const float4*>(q + qrow + off + 4);

    float m = -1e30f, l = 0.f;
    float acc[8];
#pragma unroll
    for (int d = 0; d < 8; d++) acc[d] = 0.f;

    unsigned* mrow = mask + ((b << 9) + qi) * 16;
    size_t bbase = (size_t)(b << 9) * 256;

#pragma unroll 1
    for (int w = 0; w < 16; w++) {
        unsigned bits = mrow[w];
        while (bits) {
            int bit = __ffs(bits) - 1;
            bits &= bits - 1;
            int j = (w << 5) + bit;
            size_t rbase = bbase + (size_t)j * 256 + off;
            uint4 ku = *reinterpret_cast<const uint4*>(k + rbase);
            uint4 vu = *reinterpret_cast<const uint4*>(v + rbase);
            const __half2* kh = reinterpret_cast<const __half2*>(&ku);
            const __half2* vh = reinterpret_cast<const __half2*>(&vu);
            float2 k0 = __half22float2(kh[0]);
            float2 k1 = __half22float2(kh[1]);
            float2 k2 = __half22float2(kh[2]);
            float2 k3 = __half22float2(kh[3]);

            float s = qa.x * k0.x + qa.y * k0.y + qa.z * k1.x + qa.w * k1.y
                    + qb.x * k2.x + qb.y * k2.y + qb.z * k3.x + qb.w * k3.y;
            s += __shfl_xor_sync(0xffffffffu, s, 1);
            s += __shfl_xor_sync(0xffffffffu, s, 2);
            s *= SCALE;

            float mn   = fmaxf(m, s);
            float corr = __expf(m - mn);
            float p    = __expf(s - mn);
            l = l * corr + p;
            m = mn;
            float2 v0 = __half22float2(vh[0]);
            float2 v1 = __half22float2(vh[1]);
            float2 v2 = __half22float2(vh[2]);
            float2 v3 = __half22float2(vh[3]);
            acc[0] = acc[0] * corr + p * v0.x;
            acc[1] = acc[1] * corr + p * v0.y;
            acc[2] = acc[2] * corr + p * v1.x;
            acc[3] = acc[3] * corr + p * v1.y;
            acc[4] = acc[4] * corr + p * v2.x;
            acc[5] = acc[5] * corr + p * v2.y;
            acc[6] = acc[6] * corr + p * v3.x;
            acc[7] = acc[7] * corr + p * v3.y;
        }
    }

    // restore the all-zero mask invariant for the next replay
    if (lane < 16) mrow[lane] = 0u;

    float inv = 1.f / l;
    uint4 u;
    u.x = pack_h2(__float2half_rn(acc[0] * inv), __float2half_rn(acc[1] * inv));
    u.y = pack_h2(__float2half_rn(acc[2] * inv), __float2half_rn(acc[3] * inv));
    u.z = pack_h2(__float2half_rn(acc[4] * inv), __float2half_rn(acc[5] * inv));
    u.w = pack_h2(__float2half_rn(acc[6] * inv), __float2half_rn(acc[7] * inv));
    *reinterpret_cast<uint4*>(att16 + qrow + off) = u;
}

// ---------------------------------------------------------------------------
// Launch (4 kernels total)
// ---------------------------------------------------------------------------
extern "C" void kernel_launch(void* const* d_in, const int* in_sizes, int n_in,
                              void* d_out, int out_size) {
    const float* h   = (const float*)d_in[0];
    const int*   src = (const int*)d_in[1];
    const int*   dst = (const int*)d_in[2];
    const float* Wq  = (const float*)d_in[3];
    const float* bq  = (const float*)d_in[4];
    const float* Wk  = (const float*)d_in[5];
    const float* bk  = (const float*)d_in[6];
    const float* Wv  = (const float*)d_in[7];
    const float* bv  = (const float*)d_in[8];
    const float* Wo  = (const float*)d_in[9];
    const float* bo  = (const float*)d_in[10];
    float* out = (float*)d_out;

    float *pq;
    __half *ph16, *pk16, *pv16, *patt16, *pwt;
    unsigned* pmask;
    cudaGetSymbolAddress((void**)&ph16,   g_h16);
    cudaGetSymbolAddress((void**)&pq,     g_q);
    cudaGetSymbolAddress((void**)&pk16,   g_k16);
    cudaGetSymbolAddress((void**)&pv16,   g_v16);
    cudaGetSymbolAddress((void**)&patt16, g_att16);
    cudaGetSymbolAddress((void**)&pmask,  g_mask);
    cudaGetSymbolAddress((void**)&pwt,    g_wt);

    // Prep: h fp16 + weight transpose/convert (one launch)
    prep_kernel<<<2304, 256>>>(h, Wq, Wk, Wv, Wo, ph16, pwt);

    // Q/K/V projections with fused mask build (atomics hide in issue slack)
    mma_qkv_kernel<<<dim3(MROWS / 128, 4, 3), 256>>>(
        ph16, pwt, bq, bk, bv, pq, pk16, pv16, src, dst, pmask);

    // Sparse masked attention -> fp16 output; restores mask to zero
    attn_kernel<<<MROWS / 8, 256>>>(pq, pk16, pv16, pmask, patt16);

    // Output projection straight into d_out
    mma_o_kernel<<<dim3(MROWS / 128, 4), 256>>>(patt16, pwt, bo, out);
}